// round 9
// baseline (speedup 1.0000x reference)
#include <cuda_runtime.h>
#include <cuda_fp16.h>
#include <cstdint>

// Problem constants
#define D_MODEL 1024
#define D_INNER 2048
#define NTOK    16384      // B*T
#define T_LEN   4096
#define LN_EPS  1e-5f

// ---------------------------------------------------------------------------
// Scratch (device globals — no allocation allowed)
// ---------------------------------------------------------------------------
__device__ __half g_xn  [(size_t)NTOK * D_MODEL];          // 32 MB
__device__ __half g_xz  [(size_t)NTOK * 2 * D_INNER];      // 128 MB
__device__ __half g_y   [(size_t)NTOK * D_INNER];          // 64 MB
__device__ __half g_Win [(size_t)2 * D_INNER * D_MODEL];   // 8 MB
__device__ __half g_Wout[(size_t)D_MODEL * D_INNER];       // 4 MB

// ---------------------------------------------------------------------------
// Helpers
// ---------------------------------------------------------------------------
__device__ __forceinline__ void cp_async16(uint32_t smem_addr, const void* gptr) {
    asm volatile("cp.async.cg.shared.global [%0], [%1], 16;\n"
                 :: "r"(smem_addr), "l"(gptr));
}

__device__ __forceinline__ void mma_f16_16x8x16(float* c, const uint32_t* a, const uint32_t* b) {
    asm volatile(
        "mma.sync.aligned.m16n8k16.row.col.f32.f16.f16.f32 "
        "{%0,%1,%2,%3}, {%4,%5,%6,%7}, {%8,%9}, {%0,%1,%2,%3};\n"
        : "+f"(c[0]), "+f"(c[1]), "+f"(c[2]), "+f"(c[3])
        : "r"(a[0]), "r"(a[1]), "r"(a[2]), "r"(a[3]),
          "r"(b[0]), "r"(b[1]));
}

__device__ __forceinline__ void ldsm_x4(uint32_t& r0, uint32_t& r1,
                                        uint32_t& r2, uint32_t& r3, uint32_t addr) {
    asm volatile("ldmatrix.sync.aligned.m8n8.x4.shared.b16 {%0,%1,%2,%3}, [%4];"
                 : "=r"(r0), "=r"(r1), "=r"(r2), "=r"(r3) : "r"(addr));
}

// ---------------------------------------------------------------------------
// LayerNorm -> fp16 output
// ---------------------------------------------------------------------------
__global__ void __launch_bounds__(256) ln_kernel(
    const float* __restrict__ x, const float* __restrict__ gamma,
    const float* __restrict__ beta, __half* __restrict__ xn)
{
    __shared__ float red_s[8];
    __shared__ float red_q[8];
    const int row = blockIdx.x;
    const int tid = threadIdx.x;

    const float4 v = reinterpret_cast<const float4*>(x + (size_t)row * D_MODEL)[tid];
    float s = v.x + v.y + v.z + v.w;
    float q = v.x * v.x + v.y * v.y + v.z * v.z + v.w * v.w;

    #pragma unroll
    for (int o = 16; o > 0; o >>= 1) {
        s += __shfl_xor_sync(0xFFFFFFFFu, s, o);
        q += __shfl_xor_sync(0xFFFFFFFFu, q, o);
    }
    if ((tid & 31) == 0) { red_s[tid >> 5] = s; red_q[tid >> 5] = q; }
    __syncthreads();
    if (tid < 32) {
        s = (tid < 8) ? red_s[tid] : 0.0f;
        q = (tid < 8) ? red_q[tid] : 0.0f;
        #pragma unroll
        for (int o = 4; o > 0; o >>= 1) {
            s += __shfl_xor_sync(0xFFFFFFFFu, s, o);
            q += __shfl_xor_sync(0xFFFFFFFFu, q, o);
        }
        if (tid == 0) { red_s[0] = s; red_q[0] = q; }
    }
    __syncthreads();
    const float mu   = red_s[0] * (1.0f / D_MODEL);
    const float var  = red_q[0] * (1.0f / D_MODEL) - mu * mu;
    const float rstd = rsqrtf(var + LN_EPS);

    const float4 g = reinterpret_cast<const float4*>(gamma)[tid];
    const float4 b = reinterpret_cast<const float4*>(beta)[tid];
    __half2 o0 = __floats2half2_rn((v.x - mu) * rstd * g.x + b.x,
                                   (v.y - mu) * rstd * g.y + b.y);
    __half2 o1 = __floats2half2_rn((v.z - mu) * rstd * g.z + b.z,
                                   (v.w - mu) * rstd * g.w + b.w);
    uint2 pk;
    pk.x = *reinterpret_cast<uint32_t*>(&o0);
    pk.y = *reinterpret_cast<uint32_t*>(&o1);
    reinterpret_cast<uint2*>(xn + (size_t)row * D_MODEL)[tid] = pk;
}

// ---------------------------------------------------------------------------
// fp32 -> fp16 weight conversion
// ---------------------------------------------------------------------------
__global__ void __launch_bounds__(256) cvt_half_kernel(
    const float* __restrict__ in, __half* __restrict__ out, int n4)
{
    const int i = blockIdx.x * 256 + threadIdx.x;
    if (i < n4) {
        const float4 v = reinterpret_cast<const float4*>(in)[i];
        __half2 h0 = __floats2half2_rn(v.x, v.y);
        __half2 h1 = __floats2half2_rn(v.z, v.w);
        uint2 pk;
        pk.x = *reinterpret_cast<uint32_t*>(&h0);
        pk.y = *reinterpret_cast<uint32_t*>(&h1);
        reinterpret_cast<uint2*>(out)[i] = pk;
    }
}

// ---------------------------------------------------------------------------
// Causal depthwise conv(4) + SiLU gate, fp16 in/out, fp32 math, half2 vector
// ---------------------------------------------------------------------------
__device__ __forceinline__ float silu_f(float v) { return v / (1.0f + expf(-v)); }

__global__ void __launch_bounds__(256) conv_gate_kernel(
    const __half* __restrict__ xz, const float* __restrict__ conv_w,
    const float* __restrict__ conv_b, __half* __restrict__ y)
{
    const int idx = blockIdx.x * 256 + threadIdx.x;     // over NTOK*D_INNER/2
    const int c2  = idx & (D_INNER / 2 - 1);            // half2 channel index
    const int bt  = idx >> 10;                          // / (D_INNER/2)
    const int t   = bt & (T_LEN - 1);
    const int c   = c2 * 2;

    const float4 wA = reinterpret_cast<const float4*>(conv_w)[c];
    const float4 wB = reinterpret_cast<const float4*>(conv_w)[c + 1];

    const __half2* xrow = reinterpret_cast<const __half2*>(xz) + (size_t)bt * (2 * D_INNER / 2) + c2;
    const int rs = 2 * D_INNER / 2;   // half2 row stride

    float a0 = conv_b[c], a1 = conv_b[c + 1];
    {
        const float2 v = __half22float2(xrow[0]);
        a0 += wA.w * v.x; a1 += wB.w * v.y;
    }
    if (t >= 1) { const float2 v = __half22float2(xrow[-rs]);     a0 += wA.z * v.x; a1 += wB.z * v.y; }
    if (t >= 2) { const float2 v = __half22float2(xrow[-2 * rs]); a0 += wA.y * v.x; a1 += wB.y * v.y; }
    if (t >= 3) { const float2 v = __half22float2(xrow[-3 * rs]); a0 += wA.x * v.x; a1 += wB.x * v.y; }

    const float2 z = __half22float2(xrow[D_INNER / 2]);
    const float r0 = silu_f(a0) * silu_f(z.x);
    const float r1 = silu_f(a1) * silu_f(z.y);
    reinterpret_cast<__half2*>(y)[(size_t)bt * (D_INNER / 2) + c2] = __floats2half2_rn(r0, r1);
}

// ---------------------------------------------------------------------------
// FP16 tensor-core GEMM (m16n8k16 + ldmatrix):  C[M,N] = A[M,K] * B[N,K]^T
// Tiles: BM=128, BN=128, BK=64 halves; 256 threads (8 warps 2x4), warp 64x32.
// cp.async THREE-stage pipeline, wait_group 1 -> load latency off critical path.
// smem stride 72 halves -> LDSM conflict-free.
// ---------------------------------------------------------------------------
#define BM 128
#define BN 128
#define BKH 64
#define BKP 72
#define NSTAGE 3
#define GEMM_SMEM_BYTES (NSTAGE * (BM + BN) * BKP * 2)   // 110592

// OUT_HALF=true: C is half, no residual. OUT_HALF=false: C float, += res.
template <bool OUT_HALF>
__global__ void __launch_bounds__(256, 2) gemm_f16_kernel(
    const __half* __restrict__ A,   // [M, K] row-major
    const __half* __restrict__ Bm,  // [N, K] row-major
    const float* __restrict__ res,  // [M, N] or nullptr
    void* __restrict__ Cp,          // [M, N]
    int M, int N, int K)
{
    extern __shared__ __half smem[];
    const int tid  = threadIdx.x;
    const int warp = tid >> 5;
    const int lane = tid & 31;
    const int wm = (warp & 1) * 64;
    const int wn = (warp >> 1) * 32;
    const int bm = blockIdx.y * BM;
    const int bn = blockIdx.x * BN;

    const int stage_h = (BM + BN) * BKP;   // halves per stage
    const uint32_t smemBase = (uint32_t)__cvta_generic_to_shared(smem);

    // ldmatrix lane offsets (in halves)
    const int a_lane = ((lane & 7) + ((lane >> 3) & 1) * 8) * BKP + ((lane >> 4) & 1) * 8;
    const int b_lane = (((lane >> 4) & 1) * 8 + (lane & 7)) * BKP + ((lane >> 3) & 1) * 8;

    auto load_tiles = [&](int stg, int k0) {
        uint32_t aBase = smemBase + (uint32_t)(stg * stage_h) * 2u;
        uint32_t bBase = aBase + BM * BKP * 2u;
        int idx = tid;
        #pragma unroll
        for (int i = 0; i < 4; i++, idx += 256) {
            const int r  = idx >> 3;                    // 0..127
            const int cw = idx & 7;                     // 8-half chunk
            cp_async16(aBase + (uint32_t)(r * BKP + cw * 8) * 2u,
                       A + (size_t)(bm + r) * K + k0 + cw * 8);
            cp_async16(bBase + (uint32_t)(r * BKP + cw * 8) * 2u,
                       Bm + (size_t)(bn + r) * K + k0 + cw * 8);
        }
        asm volatile("cp.async.commit_group;\n");
    };

    float acc[4][4][4];
    #pragma unroll
    for (int mt = 0; mt < 4; mt++)
        #pragma unroll
        for (int nt = 0; nt < 4; nt++)
            #pragma unroll
            for (int i = 0; i < 4; i++)
                acc[mt][nt][i] = 0.0f;

    const int KT = K / BKH;
    load_tiles(0, 0);
    load_tiles(1, BKH);

    int stg = 0;
    for (int kt = 0; kt < KT; kt++) {
        asm volatile("cp.async.wait_group 1;\n");
        __syncthreads();
        if (kt + 2 < KT) load_tiles((stg + 2) % NSTAGE, (kt + 2) * BKH);

        const uint32_t sAaddr = smemBase + (uint32_t)(stg * stage_h) * 2u;
        const uint32_t sBaddr = sAaddr + BM * BKP * 2u;

        #pragma unroll
        for (int ks = 0; ks < 4; ks++) {   // 4 k-steps of 16
            const int k0 = ks * 16;
            uint32_t af[4][4];
            uint32_t bf[4][2];
            #pragma unroll
            for (int mt = 0; mt < 4; mt++) {
                ldsm_x4(af[mt][0], af[mt][1], af[mt][2], af[mt][3],
                        sAaddr + (uint32_t)(((wm + mt * 16) * BKP + k0 + a_lane) * 2));
            }
            #pragma unroll
            for (int ntp = 0; ntp < 2; ntp++) {
                ldsm_x4(bf[2 * ntp][0], bf[2 * ntp][1], bf[2 * ntp + 1][0], bf[2 * ntp + 1][1],
                        sBaddr + (uint32_t)(((wn + ntp * 16) * BKP + k0 + b_lane) * 2));
            }
            #pragma unroll
            for (int mt = 0; mt < 4; mt++)
                #pragma unroll
                for (int nt = 0; nt < 4; nt++)
                    mma_f16_16x8x16(acc[mt][nt], af[mt], bf[nt]);
        }
        stg = (stg + 1) % NSTAGE;
    }

    // Epilogue
    const int row0 = bm + wm + (lane >> 2);
    const int col0 = bn + wn + 2 * (lane & 3);
    #pragma unroll
    for (int mt = 0; mt < 4; mt++) {
        #pragma unroll
        for (int nt = 0; nt < 4; nt++) {
            const int r  = row0 + mt * 16;
            const int cl = col0 + nt * 8;
            if (OUT_HALF) {
                __half* C = (__half*)Cp;
                *reinterpret_cast<__half2*>(C + (size_t)r * N + cl) =
                    __floats2half2_rn(acc[mt][nt][0], acc[mt][nt][1]);
                *reinterpret_cast<__half2*>(C + (size_t)(r + 8) * N + cl) =
                    __floats2half2_rn(acc[mt][nt][2], acc[mt][nt][3]);
            } else {
                float* C = (float*)Cp;
                const float2 r0 = *reinterpret_cast<const float2*>(res + (size_t)r * N + cl);
                const float2 r1 = *reinterpret_cast<const float2*>(res + (size_t)(r + 8) * N + cl);
                float2 v0 = make_float2(acc[mt][nt][0] + r0.x, acc[mt][nt][1] + r0.y);
                float2 v1 = make_float2(acc[mt][nt][2] + r1.x, acc[mt][nt][3] + r1.y);
                *reinterpret_cast<float2*>(C + (size_t)r * N + cl)       = v0;
                *reinterpret_cast<float2*>(C + (size_t)(r + 8) * N + cl) = v1;
            }
        }
    }
}

// ---------------------------------------------------------------------------
// Launch
// ---------------------------------------------------------------------------
extern "C" void kernel_launch(void* const* d_in, const int* in_sizes, int n_in,
                              void* d_out, int out_size)
{
    const float* x      = (const float*)d_in[0];
    const float* gamma  = (const float*)d_in[1];
    const float* beta   = (const float*)d_in[2];
    const float* W_in   = (const float*)d_in[3];   // [4096, 1024]
    const float* conv_w = (const float*)d_in[4];   // [2048, 1, 4]
    const float* conv_b = (const float*)d_in[5];   // [2048]
    const float* W_out  = (const float*)d_in[6];   // [1024, 2048]
    float* out = (float*)d_out;                    // [NTOK, 1024]

    __half *xn, *xz, *y, *Win, *Wout;
    cudaGetSymbolAddress((void**)&xn,   g_xn);
    cudaGetSymbolAddress((void**)&xz,   g_xz);
    cudaGetSymbolAddress((void**)&y,    g_y);
    cudaGetSymbolAddress((void**)&Win,  g_Win);
    cudaGetSymbolAddress((void**)&Wout, g_Wout);

    cudaFuncSetAttribute(gemm_f16_kernel<true>,
                         cudaFuncAttributeMaxDynamicSharedMemorySize, GEMM_SMEM_BYTES);
    cudaFuncSetAttribute(gemm_f16_kernel<false>,
                         cudaFuncAttributeMaxDynamicSharedMemorySize, GEMM_SMEM_BYTES);

    // 0) fp16 weight conversion (one pass)
    {
        const int n4_in  = (2 * D_INNER * D_MODEL) / 4;
        const int n4_out = (D_MODEL * D_INNER) / 4;
        cvt_half_kernel<<<(n4_in  + 255) / 256, 256>>>(W_in,  Win,  n4_in);
        cvt_half_kernel<<<(n4_out + 255) / 256, 256>>>(W_out, Wout, n4_out);
    }

    // 1) LayerNorm (fp16 output)
    ln_kernel<<<NTOK, 256>>>(x, gamma, beta, xn);

    // 2) in_proj GEMM: xz[16384,4096] (fp16) = xn @ Win^T
    {
        dim3 grid(2 * D_INNER / BN, NTOK / BM);   // (32, 128)
        gemm_f16_kernel<true><<<grid, 256, GEMM_SMEM_BYTES>>>(
            xn, Win, nullptr, xz, NTOK, 2 * D_INNER, D_MODEL);
    }

    // 3) causal depthwise conv + SiLU gate (fp16 y)
    conv_gate_kernel<<<(NTOK * D_INNER / 2) / 256, 256>>>(xz, conv_w, conv_b, y);

    // 4) out_proj GEMM + residual: out = x + y @ Wout^T (fp32 output)
    {
        dim3 grid(D_MODEL / BN, NTOK / BM);       // (8, 128)
        gemm_f16_kernel<false><<<grid, 256, GEMM_SMEM_BYTES>>>(
            y, Wout, x, out, NTOK, D_MODEL, D_INNER);
    }
}

// round 10
// speedup vs baseline: 1.0203x; 1.0203x over previous
#include <cuda_runtime.h>
#include <cuda_fp16.h>
#include <cstdint>

// Problem constants
#define D_MODEL 1024
#define D_INNER 2048
#define NTOK    16384      // B*T
#define T_LEN   4096
#define LN_EPS  1e-5f

// ---------------------------------------------------------------------------
// Scratch (device globals — no allocation allowed)
// ---------------------------------------------------------------------------
__device__ __half g_xn  [(size_t)NTOK * D_MODEL];          // 32 MB
__device__ __half g_xz  [(size_t)NTOK * 2 * D_INNER];      // 128 MB
__device__ __half g_y   [(size_t)NTOK * D_INNER];          // 64 MB
__device__ __half g_Win [(size_t)2 * D_INNER * D_MODEL];   // 8 MB
__device__ __half g_Wout[(size_t)D_MODEL * D_INNER];       // 4 MB

// ---------------------------------------------------------------------------
// Helpers
// ---------------------------------------------------------------------------
__device__ __forceinline__ void cp_async16(uint32_t smem_addr, const void* gptr) {
    asm volatile("cp.async.cg.shared.global [%0], [%1], 16;\n"
                 :: "r"(smem_addr), "l"(gptr));
}

__device__ __forceinline__ void mma_f16_16x8x16(float* c, const uint32_t* a, const uint32_t* b) {
    asm volatile(
        "mma.sync.aligned.m16n8k16.row.col.f32.f16.f16.f32 "
        "{%0,%1,%2,%3}, {%4,%5,%6,%7}, {%8,%9}, {%0,%1,%2,%3};\n"
        : "+f"(c[0]), "+f"(c[1]), "+f"(c[2]), "+f"(c[3])
        : "r"(a[0]), "r"(a[1]), "r"(a[2]), "r"(a[3]),
          "r"(b[0]), "r"(b[1]));
}

__device__ __forceinline__ void ldsm_x4(uint32_t& r0, uint32_t& r1,
                                        uint32_t& r2, uint32_t& r3, uint32_t addr) {
    asm volatile("ldmatrix.sync.aligned.m8n8.x4.shared.b16 {%0,%1,%2,%3}, [%4];"
                 : "=r"(r0), "=r"(r1), "=r"(r2), "=r"(r3) : "r"(addr));
}

// ---------------------------------------------------------------------------
// LayerNorm -> fp16 output
// ---------------------------------------------------------------------------
__global__ void __launch_bounds__(256) ln_kernel(
    const float* __restrict__ x, const float* __restrict__ gamma,
    const float* __restrict__ beta, __half* __restrict__ xn)
{
    __shared__ float red_s[8];
    __shared__ float red_q[8];
    const int row = blockIdx.x;
    const int tid = threadIdx.x;

    const float4 v = reinterpret_cast<const float4*>(x + (size_t)row * D_MODEL)[tid];
    float s = v.x + v.y + v.z + v.w;
    float q = v.x * v.x + v.y * v.y + v.z * v.z + v.w * v.w;

    #pragma unroll
    for (int o = 16; o > 0; o >>= 1) {
        s += __shfl_xor_sync(0xFFFFFFFFu, s, o);
        q += __shfl_xor_sync(0xFFFFFFFFu, q, o);
    }
    if ((tid & 31) == 0) { red_s[tid >> 5] = s; red_q[tid >> 5] = q; }
    __syncthreads();
    if (tid < 32) {
        s = (tid < 8) ? red_s[tid] : 0.0f;
        q = (tid < 8) ? red_q[tid] : 0.0f;
        #pragma unroll
        for (int o = 4; o > 0; o >>= 1) {
            s += __shfl_xor_sync(0xFFFFFFFFu, s, o);
            q += __shfl_xor_sync(0xFFFFFFFFu, q, o);
        }
        if (tid == 0) { red_s[0] = s; red_q[0] = q; }
    }
    __syncthreads();
    const float mu   = red_s[0] * (1.0f / D_MODEL);
    const float var  = red_q[0] * (1.0f / D_MODEL) - mu * mu;
    const float rstd = rsqrtf(var + LN_EPS);

    const float4 g = reinterpret_cast<const float4*>(gamma)[tid];
    const float4 b = reinterpret_cast<const float4*>(beta)[tid];
    __half2 o0 = __floats2half2_rn((v.x - mu) * rstd * g.x + b.x,
                                   (v.y - mu) * rstd * g.y + b.y);
    __half2 o1 = __floats2half2_rn((v.z - mu) * rstd * g.z + b.z,
                                   (v.w - mu) * rstd * g.w + b.w);
    uint2 pk;
    pk.x = *reinterpret_cast<uint32_t*>(&o0);
    pk.y = *reinterpret_cast<uint32_t*>(&o1);
    reinterpret_cast<uint2*>(xn + (size_t)row * D_MODEL)[tid] = pk;
}

// ---------------------------------------------------------------------------
// fp32 -> fp16 weight conversion
// ---------------------------------------------------------------------------
__global__ void __launch_bounds__(256) cvt_half_kernel(
    const float* __restrict__ in, __half* __restrict__ out, int n4)
{
    const int i = blockIdx.x * 256 + threadIdx.x;
    if (i < n4) {
        const float4 v = reinterpret_cast<const float4*>(in)[i];
        __half2 h0 = __floats2half2_rn(v.x, v.y);
        __half2 h1 = __floats2half2_rn(v.z, v.w);
        uint2 pk;
        pk.x = *reinterpret_cast<uint32_t*>(&h0);
        pk.y = *reinterpret_cast<uint32_t*>(&h1);
        reinterpret_cast<uint2*>(out)[i] = pk;
    }
}

// ---------------------------------------------------------------------------
// Causal depthwise conv(4) + SiLU gate, fp16 in/out, fp32 math, half2 vector
// ---------------------------------------------------------------------------
__device__ __forceinline__ float silu_f(float v) { return v / (1.0f + expf(-v)); }

__global__ void __launch_bounds__(256) conv_gate_kernel(
    const __half* __restrict__ xz, const float* __restrict__ conv_w,
    const float* __restrict__ conv_b, __half* __restrict__ y)
{
    const int idx = blockIdx.x * 256 + threadIdx.x;     // over NTOK*D_INNER/2
    const int c2  = idx & (D_INNER / 2 - 1);            // half2 channel index
    const int bt  = idx >> 10;                          // / (D_INNER/2)
    const int t   = bt & (T_LEN - 1);
    const int c   = c2 * 2;

    const float4 wA = reinterpret_cast<const float4*>(conv_w)[c];
    const float4 wB = reinterpret_cast<const float4*>(conv_w)[c + 1];

    const __half2* xrow = reinterpret_cast<const __half2*>(xz) + (size_t)bt * (2 * D_INNER / 2) + c2;
    const int rs = 2 * D_INNER / 2;   // half2 row stride

    float a0 = conv_b[c], a1 = conv_b[c + 1];
    {
        const float2 v = __half22float2(xrow[0]);
        a0 += wA.w * v.x; a1 += wB.w * v.y;
    }
    if (t >= 1) { const float2 v = __half22float2(xrow[-rs]);     a0 += wA.z * v.x; a1 += wB.z * v.y; }
    if (t >= 2) { const float2 v = __half22float2(xrow[-2 * rs]); a0 += wA.y * v.x; a1 += wB.y * v.y; }
    if (t >= 3) { const float2 v = __half22float2(xrow[-3 * rs]); a0 += wA.x * v.x; a1 += wB.x * v.y; }

    const float2 z = __half22float2(xrow[D_INNER / 2]);
    const float r0 = silu_f(a0) * silu_f(z.x);
    const float r1 = silu_f(a1) * silu_f(z.y);
    reinterpret_cast<__half2*>(y)[(size_t)bt * (D_INNER / 2) + c2] = __floats2half2_rn(r0, r1);
}

// ---------------------------------------------------------------------------
// FP16 tensor-core GEMM (m16n8k16 + ldmatrix):  C[M,N] = A[M,K] * B[N,K]^T
// Tiles: BM=128, BN=128, BK=64 halves; 512 threads (16 warps 4x4), warp 32x32.
// Small per-warp state (~60 regs) -> 2 CTAs/SM = 32 warps = 8/SMSP.
// cp.async 3-stage; smem stride 72 halves -> LDSM conflict-free.
// ---------------------------------------------------------------------------
#define BM 128
#define BN 128
#define BKH 64
#define BKP 72
#define NSTAGE 3
#define GEMM_SMEM_BYTES (NSTAGE * (BM + BN) * BKP * 2)   // 110592

// OUT_HALF=true: C is half, no residual. OUT_HALF=false: C float, += res.
template <bool OUT_HALF>
__global__ void __launch_bounds__(512, 2) gemm_f16_kernel(
    const __half* __restrict__ A,   // [M, K] row-major
    const __half* __restrict__ Bm,  // [N, K] row-major
    const float* __restrict__ res,  // [M, N] or nullptr
    void* __restrict__ Cp,          // [M, N]
    int M, int N, int K)
{
    extern __shared__ __half smem[];
    const int tid  = threadIdx.x;
    const int warp = tid >> 5;
    const int lane = tid & 31;
    const int wm = (warp & 3) * 32;    // 4 warp-rows
    const int wn = (warp >> 2) * 32;   // 4 warp-cols
    const int bm = blockIdx.y * BM;
    const int bn = blockIdx.x * BN;

    const int stage_h = (BM + BN) * BKP;   // halves per stage
    const uint32_t smemBase = (uint32_t)__cvta_generic_to_shared(smem);

    // ldmatrix lane offsets (in halves)
    // A x4: m0=rows0-7/k0-7, m1=rows8-15/k0-7, m2=rows0-7/k8-15, m3=rows8-15/k8-15
    const int a_lane = ((lane & 7) + ((lane >> 3) & 1) * 8) * BKP + ((lane >> 4) & 1) * 8;
    // B x4: m0=n0-7/k0-7, m1=n0-7/k8-15, m2=n8-15/k0-7, m3=n8-15/k8-15
    const int b_lane = (((lane >> 4) & 1) * 8 + (lane & 7)) * BKP + ((lane >> 3) & 1) * 8;

    auto load_tiles = [&](int stg, int k0) {
        uint32_t aBase = smemBase + (uint32_t)(stg * stage_h) * 2u;
        uint32_t bBase = aBase + BM * BKP * 2u;
        int idx = tid;
        #pragma unroll
        for (int i = 0; i < 2; i++, idx += 512) {       // 1024 chunks of 16B each side
            const int r  = idx >> 3;                    // 0..127
            const int cw = idx & 7;                     // 8-half chunk
            cp_async16(aBase + (uint32_t)(r * BKP + cw * 8) * 2u,
                       A + (size_t)(bm + r) * K + k0 + cw * 8);
            cp_async16(bBase + (uint32_t)(r * BKP + cw * 8) * 2u,
                       Bm + (size_t)(bn + r) * K + k0 + cw * 8);
        }
        asm volatile("cp.async.commit_group;\n");
    };

    float acc[2][4][4];
    #pragma unroll
    for (int mt = 0; mt < 2; mt++)
        #pragma unroll
        for (int nt = 0; nt < 4; nt++)
            #pragma unroll
            for (int i = 0; i < 4; i++)
                acc[mt][nt][i] = 0.0f;

    const int KT = K / BKH;
    load_tiles(0, 0);
    load_tiles(1, BKH);

    int stg = 0;
    for (int kt = 0; kt < KT; kt++) {
        asm volatile("cp.async.wait_group 1;\n");
        __syncthreads();
        if (kt + 2 < KT) load_tiles((stg + 2) % NSTAGE, (kt + 2) * BKH);

        const uint32_t sAaddr = smemBase + (uint32_t)(stg * stage_h) * 2u;
        const uint32_t sBaddr = sAaddr + BM * BKP * 2u;

        #pragma unroll
        for (int ks = 0; ks < 4; ks++) {   // 4 k-steps of 16
            const int k0 = ks * 16;
            uint32_t af[2][4];
            uint32_t bf[4][2];
            #pragma unroll
            for (int mt = 0; mt < 2; mt++) {
                ldsm_x4(af[mt][0], af[mt][1], af[mt][2], af[mt][3],
                        sAaddr + (uint32_t)(((wm + mt * 16) * BKP + k0 + a_lane) * 2));
            }
            #pragma unroll
            for (int ntp = 0; ntp < 2; ntp++) {
                ldsm_x4(bf[2 * ntp][0], bf[2 * ntp][1], bf[2 * ntp + 1][0], bf[2 * ntp + 1][1],
                        sBaddr + (uint32_t)(((wn + ntp * 16) * BKP + k0 + b_lane) * 2));
            }
            #pragma unroll
            for (int mt = 0; mt < 2; mt++)
                #pragma unroll
                for (int nt = 0; nt < 4; nt++)
                    mma_f16_16x8x16(acc[mt][nt], af[mt], bf[nt]);
        }
        stg = (stg + 1) % NSTAGE;
    }

    // Epilogue
    const int row0 = bm + wm + (lane >> 2);
    const int col0 = bn + wn + 2 * (lane & 3);
    #pragma unroll
    for (int mt = 0; mt < 2; mt++) {
        #pragma unroll
        for (int nt = 0; nt < 4; nt++) {
            const int r  = row0 + mt * 16;
            const int cl = col0 + nt * 8;
            if (OUT_HALF) {
                __half* C = (__half*)Cp;
                *reinterpret_cast<__half2*>(C + (size_t)r * N + cl) =
                    __floats2half2_rn(acc[mt][nt][0], acc[mt][nt][1]);
                *reinterpret_cast<__half2*>(C + (size_t)(r + 8) * N + cl) =
                    __floats2half2_rn(acc[mt][nt][2], acc[mt][nt][3]);
            } else {
                float* C = (float*)Cp;
                const float2 r0 = *reinterpret_cast<const float2*>(res + (size_t)r * N + cl);
                const float2 r1 = *reinterpret_cast<const float2*>(res + (size_t)(r + 8) * N + cl);
                float2 v0 = make_float2(acc[mt][nt][0] + r0.x, acc[mt][nt][1] + r0.y);
                float2 v1 = make_float2(acc[mt][nt][2] + r1.x, acc[mt][nt][3] + r1.y);
                *reinterpret_cast<float2*>(C + (size_t)r * N + cl)       = v0;
                *reinterpret_cast<float2*>(C + (size_t)(r + 8) * N + cl) = v1;
            }
        }
    }
}

// ---------------------------------------------------------------------------
// Launch
// ---------------------------------------------------------------------------
extern "C" void kernel_launch(void* const* d_in, const int* in_sizes, int n_in,
                              void* d_out, int out_size)
{
    const float* x      = (const float*)d_in[0];
    const float* gamma  = (const float*)d_in[1];
    const float* beta   = (const float*)d_in[2];
    const float* W_in   = (const float*)d_in[3];   // [4096, 1024]
    const float* conv_w = (const float*)d_in[4];   // [2048, 1, 4]
    const float* conv_b = (const float*)d_in[5];   // [2048]
    const float* W_out  = (const float*)d_in[6];   // [1024, 2048]
    float* out = (float*)d_out;                    // [NTOK, 1024]

    __half *xn, *xz, *y, *Win, *Wout;
    cudaGetSymbolAddress((void**)&xn,   g_xn);
    cudaGetSymbolAddress((void**)&xz,   g_xz);
    cudaGetSymbolAddress((void**)&y,    g_y);
    cudaGetSymbolAddress((void**)&Win,  g_Win);
    cudaGetSymbolAddress((void**)&Wout, g_Wout);

    cudaFuncSetAttribute(gemm_f16_kernel<true>,
                         cudaFuncAttributeMaxDynamicSharedMemorySize, GEMM_SMEM_BYTES);
    cudaFuncSetAttribute(gemm_f16_kernel<false>,
                         cudaFuncAttributeMaxDynamicSharedMemorySize, GEMM_SMEM_BYTES);

    // 0) fp16 weight conversion (one pass)
    {
        const int n4_in  = (2 * D_INNER * D_MODEL) / 4;
        const int n4_out = (D_MODEL * D_INNER) / 4;
        cvt_half_kernel<<<(n4_in  + 255) / 256, 256>>>(W_in,  Win,  n4_in);
        cvt_half_kernel<<<(n4_out + 255) / 256, 256>>>(W_out, Wout, n4_out);
    }

    // 1) LayerNorm (fp16 output)
    ln_kernel<<<NTOK, 256>>>(x, gamma, beta, xn);

    // 2) in_proj GEMM: xz[16384,4096] (fp16) = xn @ Win^T
    {
        dim3 grid(2 * D_INNER / BN, NTOK / BM);   // (32, 128)
        gemm_f16_kernel<true><<<grid, 512, GEMM_SMEM_BYTES>>>(
            xn, Win, nullptr, xz, NTOK, 2 * D_INNER, D_MODEL);
    }

    // 3) causal depthwise conv + SiLU gate (fp16 y)
    conv_gate_kernel<<<(NTOK * D_INNER / 2) / 256, 256>>>(xz, conv_w, conv_b, y);

    // 4) out_proj GEMM + residual: out = x + y @ Wout^T (fp32 output)
    {
        dim3 grid(D_MODEL / BN, NTOK / BM);       // (8, 128)
        gemm_f16_kernel<false><<<grid, 512, GEMM_SMEM_BYTES>>>(
            y, Wout, x, out, NTOK, D_MODEL, D_INNER);
    }
}

// round 11
// speedup vs baseline: 1.0876x; 1.0660x over previous
#include <cuda_runtime.h>
#include <cuda_fp16.h>
#include <cstdint>

// Problem constants
#define D_MODEL 1024
#define D_INNER 2048
#define NTOK    16384      // B*T
#define T_LEN   4096
#define LN_EPS  1e-5f

// ---------------------------------------------------------------------------
// Scratch (device globals — no allocation allowed)
// ---------------------------------------------------------------------------
__device__ __half g_xn   [(size_t)NTOK * D_MODEL];          // 32 MB
__device__ __half g_xz   [(size_t)NTOK * 2 * D_INNER];      // 128 MB
__device__ __half g_y    [(size_t)NTOK * D_INNER];          // 64 MB
__device__ __half g_Win  [(size_t)2 * D_INNER * D_MODEL];   // 8 MB
__device__ __half g_Wout [(size_t)D_MODEL * D_INNER];       // 4 MB
__device__ __half g_wpack[5 * D_INNER];                     // taps 0-3 + bias

// ---------------------------------------------------------------------------
// Helpers
// ---------------------------------------------------------------------------
__device__ __forceinline__ void cp_async16(uint32_t smem_addr, const void* gptr) {
    asm volatile("cp.async.cg.shared.global [%0], [%1], 16;\n"
                 :: "r"(smem_addr), "l"(gptr));
}

__device__ __forceinline__ void mma_f16_16x8x16(float* c, const uint32_t* a, const uint32_t* b) {
    asm volatile(
        "mma.sync.aligned.m16n8k16.row.col.f32.f16.f16.f32 "
        "{%0,%1,%2,%3}, {%4,%5,%6,%7}, {%8,%9}, {%0,%1,%2,%3};\n"
        : "+f"(c[0]), "+f"(c[1]), "+f"(c[2]), "+f"(c[3])
        : "r"(a[0]), "r"(a[1]), "r"(a[2]), "r"(a[3]),
          "r"(b[0]), "r"(b[1]));
}

__device__ __forceinline__ void ldsm_x4(uint32_t& r0, uint32_t& r1,
                                        uint32_t& r2, uint32_t& r3, uint32_t addr) {
    asm volatile("ldmatrix.sync.aligned.m8n8.x4.shared.b16 {%0,%1,%2,%3}, [%4];"
                 : "=r"(r0), "=r"(r1), "=r"(r2), "=r"(r3) : "r"(addr));
}

__device__ __forceinline__ void stcs_u32(void* p, uint32_t v) {
    asm volatile("st.global.cs.u32 [%0], %1;" :: "l"(p), "r"(v) : "memory");
}
__device__ __forceinline__ void stcs_f32x2(void* p, float a, float b) {
    asm volatile("st.global.cs.v2.f32 [%0], {%1, %2};" :: "l"(p), "f"(a), "f"(b) : "memory");
}

// fast silu: v * sigmoid(v) with guaranteed MUFU path
__device__ __forceinline__ float silu_fast(float v) {
    return __fdividef(v, 1.0f + __expf(-v));
}

// ---------------------------------------------------------------------------
// Fused prep: Win->fp16, Wout->fp16, conv weight/bias pack (fp16 rows)
// grid = 4096 + 2048 + 1 blocks of 256 threads
// ---------------------------------------------------------------------------
__global__ void __launch_bounds__(256) prep_kernel(
    const float* __restrict__ W_in, const float* __restrict__ W_out,
    const float* __restrict__ conv_w, const float* __restrict__ conv_b,
    __half* __restrict__ Win, __half* __restrict__ Wout, __half* __restrict__ wpack)
{
    const int bid = blockIdx.x;
    const int tid = threadIdx.x;
    if (bid < 4096) {                              // Win: 1048576 float4
        const int i = bid * 256 + tid;
        const float4 v = reinterpret_cast<const float4*>(W_in)[i];
        __half2 h0 = __floats2half2_rn(v.x, v.y);
        __half2 h1 = __floats2half2_rn(v.z, v.w);
        uint2 pk = make_uint2(*reinterpret_cast<uint32_t*>(&h0),
                              *reinterpret_cast<uint32_t*>(&h1));
        reinterpret_cast<uint2*>(Win)[i] = pk;
    } else if (bid < 6144) {                       // Wout: 524288 float4
        const int i = (bid - 4096) * 256 + tid;
        const float4 v = reinterpret_cast<const float4*>(W_out)[i];
        __half2 h0 = __floats2half2_rn(v.x, v.y);
        __half2 h1 = __floats2half2_rn(v.z, v.w);
        uint2 pk = make_uint2(*reinterpret_cast<uint32_t*>(&h0),
                              *reinterpret_cast<uint32_t*>(&h1));
        reinterpret_cast<uint2*>(Wout)[i] = pk;
    } else {                                       // wpack: 2048 channels, 8 per thread
        #pragma unroll
        for (int j = 0; j < 8; j++) {
            const int c = tid * 8 + j;
            #pragma unroll
            for (int k = 0; k < 4; k++)
                wpack[k * D_INNER + c] = __float2half_rn(conv_w[c * 4 + k]);
            wpack[4 * D_INNER + c] = __float2half_rn(conv_b[c]);
        }
    }
}

// ---------------------------------------------------------------------------
// LayerNorm -> fp16 output
// ---------------------------------------------------------------------------
__global__ void __launch_bounds__(256) ln_kernel(
    const float* __restrict__ x, const float* __restrict__ gamma,
    const float* __restrict__ beta, __half* __restrict__ xn)
{
    __shared__ float red_s[8];
    __shared__ float red_q[8];
    const int row = blockIdx.x;
    const int tid = threadIdx.x;

    const float4 v = reinterpret_cast<const float4*>(x + (size_t)row * D_MODEL)[tid];
    float s = v.x + v.y + v.z + v.w;
    float q = v.x * v.x + v.y * v.y + v.z * v.z + v.w * v.w;

    #pragma unroll
    for (int o = 16; o > 0; o >>= 1) {
        s += __shfl_xor_sync(0xFFFFFFFFu, s, o);
        q += __shfl_xor_sync(0xFFFFFFFFu, q, o);
    }
    if ((tid & 31) == 0) { red_s[tid >> 5] = s; red_q[tid >> 5] = q; }
    __syncthreads();
    if (tid < 32) {
        s = (tid < 8) ? red_s[tid] : 0.0f;
        q = (tid < 8) ? red_q[tid] : 0.0f;
        #pragma unroll
        for (int o = 4; o > 0; o >>= 1) {
            s += __shfl_xor_sync(0xFFFFFFFFu, s, o);
            q += __shfl_xor_sync(0xFFFFFFFFu, q, o);
        }
        if (tid == 0) { red_s[0] = s; red_q[0] = q; }
    }
    __syncthreads();
    const float mu   = red_s[0] * (1.0f / D_MODEL);
    const float var  = red_q[0] * (1.0f / D_MODEL) - mu * mu;
    const float rstd = rsqrtf(var + LN_EPS);

    const float4 g = reinterpret_cast<const float4*>(gamma)[tid];
    const float4 b = reinterpret_cast<const float4*>(beta)[tid];
    __half2 o0 = __floats2half2_rn((v.x - mu) * rstd * g.x + b.x,
                                   (v.y - mu) * rstd * g.y + b.y);
    __half2 o1 = __floats2half2_rn((v.z - mu) * rstd * g.z + b.z,
                                   (v.w - mu) * rstd * g.w + b.w);
    uint2 pk;
    pk.x = *reinterpret_cast<uint32_t*>(&o0);
    pk.y = *reinterpret_cast<uint32_t*>(&o1);
    reinterpret_cast<uint2*>(xn + (size_t)row * D_MODEL)[tid] = pk;
}

// ---------------------------------------------------------------------------
// Causal depthwise conv(4) + SiLU gate: one block per token, 8 channels/thread.
// fp16 loads (uint4), fp32 math, fast MUFU silu, fp16 packed weights.
// ---------------------------------------------------------------------------
__device__ __forceinline__ void unpack8(uint4 u, float* f) {
    const __half2* h = reinterpret_cast<const __half2*>(&u);
    #pragma unroll
    for (int i = 0; i < 4; i++) {
        const float2 v = __half22float2(h[i]);
        f[2 * i] = v.x; f[2 * i + 1] = v.y;
    }
}

__global__ void __launch_bounds__(256) conv_gate_kernel(
    const __half* __restrict__ xz, const __half* __restrict__ wpack,
    __half* __restrict__ y)
{
    const int bt = blockIdx.x;
    const int t  = bt & (T_LEN - 1);
    const int c  = threadIdx.x * 8;

    const __half* base = xz + (size_t)bt * (2 * D_INNER) + c;

    float w0[8], w1[8], w2[8], w3[8], bs[8];
    unpack8(*reinterpret_cast<const uint4*>(wpack + 0 * D_INNER + c), w0);
    unpack8(*reinterpret_cast<const uint4*>(wpack + 1 * D_INNER + c), w1);
    unpack8(*reinterpret_cast<const uint4*>(wpack + 2 * D_INNER + c), w2);
    unpack8(*reinterpret_cast<const uint4*>(wpack + 3 * D_INNER + c), w3);
    unpack8(*reinterpret_cast<const uint4*>(wpack + 4 * D_INNER + c), bs);

    float acc[8];
    {
        float cur[8];
        unpack8(*reinterpret_cast<const uint4*>(base), cur);
        #pragma unroll
        for (int i = 0; i < 8; i++) acc[i] = bs[i] + w3[i] * cur[i];
    }
    if (t >= 1) {
        float p[8];
        unpack8(*reinterpret_cast<const uint4*>(base - 2 * D_INNER), p);
        #pragma unroll
        for (int i = 0; i < 8; i++) acc[i] += w2[i] * p[i];
    }
    if (t >= 2) {
        float p[8];
        unpack8(*reinterpret_cast<const uint4*>(base - 4 * D_INNER), p);
        #pragma unroll
        for (int i = 0; i < 8; i++) acc[i] += w1[i] * p[i];
    }
    if (t >= 3) {
        float p[8];
        unpack8(*reinterpret_cast<const uint4*>(base - 6 * D_INNER), p);
        #pragma unroll
        for (int i = 0; i < 8; i++) acc[i] += w0[i] * p[i];
    }

    float z[8];
    unpack8(*reinterpret_cast<const uint4*>(base + D_INNER), z);

    uint4 out;
    __half2* oh = reinterpret_cast<__half2*>(&out);
    #pragma unroll
    for (int i = 0; i < 4; i++) {
        const float r0 = silu_fast(acc[2 * i])     * silu_fast(z[2 * i]);
        const float r1 = silu_fast(acc[2 * i + 1]) * silu_fast(z[2 * i + 1]);
        oh[i] = __floats2half2_rn(r0, r1);
    }
    *reinterpret_cast<uint4*>(y + (size_t)bt * D_INNER + c) = out;
}

// ---------------------------------------------------------------------------
// FP16 tensor-core GEMM (m16n8k16 + ldmatrix):  C[M,N] = A[M,K] * B[N,K]^T
// Tiles: BM=128, BN=128, BK=64 halves; 512 threads (16 warps 4x4), warp 32x32.
// 2 CTAs/SM; cp.async 3-stage; smem stride 72 -> LDSM conflict-free.
// ---------------------------------------------------------------------------
#define BM 128
#define BN 128
#define BKH 64
#define BKP 72
#define NSTAGE 3
#define GEMM_SMEM_BYTES (NSTAGE * (BM + BN) * BKP * 2)   // 110592

// OUT_HALF=true: C is half (streaming store), no residual.
// OUT_HALF=false: C float, += res (streaming store).
template <bool OUT_HALF>
__global__ void __launch_bounds__(512, 2) gemm_f16_kernel(
    const __half* __restrict__ A,   // [M, K] row-major
    const __half* __restrict__ Bm,  // [N, K] row-major
    const float* __restrict__ res,  // [M, N] or nullptr
    void* __restrict__ Cp,          // [M, N]
    int M, int N, int K)
{
    extern __shared__ __half smem[];
    const int tid  = threadIdx.x;
    const int warp = tid >> 5;
    const int lane = tid & 31;
    const int wm = (warp & 3) * 32;    // 4 warp-rows
    const int wn = (warp >> 2) * 32;   // 4 warp-cols
    const int bm = blockIdx.y * BM;
    const int bn = blockIdx.x * BN;

    const int stage_h = (BM + BN) * BKP;   // halves per stage
    const uint32_t smemBase = (uint32_t)__cvta_generic_to_shared(smem);

    const int a_lane = ((lane & 7) + ((lane >> 3) & 1) * 8) * BKP + ((lane >> 4) & 1) * 8;
    const int b_lane = (((lane >> 4) & 1) * 8 + (lane & 7)) * BKP + ((lane >> 3) & 1) * 8;

    auto load_tiles = [&](int stg, int k0) {
        uint32_t aBase = smemBase + (uint32_t)(stg * stage_h) * 2u;
        uint32_t bBase = aBase + BM * BKP * 2u;
        int idx = tid;
        #pragma unroll
        for (int i = 0; i < 2; i++, idx += 512) {
            const int r  = idx >> 3;
            const int cw = idx & 7;
            cp_async16(aBase + (uint32_t)(r * BKP + cw * 8) * 2u,
                       A + (size_t)(bm + r) * K + k0 + cw * 8);
            cp_async16(bBase + (uint32_t)(r * BKP + cw * 8) * 2u,
                       Bm + (size_t)(bn + r) * K + k0 + cw * 8);
        }
        asm volatile("cp.async.commit_group;\n");
    };

    float acc[2][4][4];
    #pragma unroll
    for (int mt = 0; mt < 2; mt++)
        #pragma unroll
        for (int nt = 0; nt < 4; nt++)
            #pragma unroll
            for (int i = 0; i < 4; i++)
                acc[mt][nt][i] = 0.0f;

    const int KT = K / BKH;
    load_tiles(0, 0);
    load_tiles(1, BKH);

    int stg = 0;
    for (int kt = 0; kt < KT; kt++) {
        asm volatile("cp.async.wait_group 1;\n");
        __syncthreads();
        if (kt + 2 < KT) load_tiles((stg + 2) % NSTAGE, (kt + 2) * BKH);

        const uint32_t sAaddr = smemBase + (uint32_t)(stg * stage_h) * 2u;
        const uint32_t sBaddr = sAaddr + BM * BKP * 2u;

        #pragma unroll
        for (int ks = 0; ks < 4; ks++) {
            const int k0 = ks * 16;
            uint32_t af[2][4];
            uint32_t bf[4][2];
            #pragma unroll
            for (int mt = 0; mt < 2; mt++) {
                ldsm_x4(af[mt][0], af[mt][1], af[mt][2], af[mt][3],
                        sAaddr + (uint32_t)(((wm + mt * 16) * BKP + k0 + a_lane) * 2));
            }
            #pragma unroll
            for (int ntp = 0; ntp < 2; ntp++) {
                ldsm_x4(bf[2 * ntp][0], bf[2 * ntp][1], bf[2 * ntp + 1][0], bf[2 * ntp + 1][1],
                        sBaddr + (uint32_t)(((wn + ntp * 16) * BKP + k0 + b_lane) * 2));
            }
            #pragma unroll
            for (int mt = 0; mt < 2; mt++)
                #pragma unroll
                for (int nt = 0; nt < 4; nt++)
                    mma_f16_16x8x16(acc[mt][nt], af[mt], bf[nt]);
        }
        stg = (stg + 1) % NSTAGE;
    }

    // Epilogue (streaming stores — outputs are not re-read through L2 soon)
    const int row0 = bm + wm + (lane >> 2);
    const int col0 = bn + wn + 2 * (lane & 3);
    #pragma unroll
    for (int mt = 0; mt < 2; mt++) {
        #pragma unroll
        for (int nt = 0; nt < 4; nt++) {
            const int r  = row0 + mt * 16;
            const int cl = col0 + nt * 8;
            if (OUT_HALF) {
                __half* C = (__half*)Cp;
                __half2 v0 = __floats2half2_rn(acc[mt][nt][0], acc[mt][nt][1]);
                __half2 v1 = __floats2half2_rn(acc[mt][nt][2], acc[mt][nt][3]);
                stcs_u32(C + (size_t)r * N + cl,       *reinterpret_cast<uint32_t*>(&v0));
                stcs_u32(C + (size_t)(r + 8) * N + cl, *reinterpret_cast<uint32_t*>(&v1));
            } else {
                float* C = (float*)Cp;
                const float2 r0 = *reinterpret_cast<const float2*>(res + (size_t)r * N + cl);
                const float2 r1 = *reinterpret_cast<const float2*>(res + (size_t)(r + 8) * N + cl);
                stcs_f32x2(C + (size_t)r * N + cl,       acc[mt][nt][0] + r0.x, acc[mt][nt][1] + r0.y);
                stcs_f32x2(C + (size_t)(r + 8) * N + cl, acc[mt][nt][2] + r1.x, acc[mt][nt][3] + r1.y);
            }
        }
    }
}

// ---------------------------------------------------------------------------
// Launch
// ---------------------------------------------------------------------------
extern "C" void kernel_launch(void* const* d_in, const int* in_sizes, int n_in,
                              void* d_out, int out_size)
{
    const float* x      = (const float*)d_in[0];
    const float* gamma  = (const float*)d_in[1];
    const float* beta   = (const float*)d_in[2];
    const float* W_in   = (const float*)d_in[3];   // [4096, 1024]
    const float* conv_w = (const float*)d_in[4];   // [2048, 1, 4]
    const float* conv_b = (const float*)d_in[5];   // [2048]
    const float* W_out  = (const float*)d_in[6];   // [1024, 2048]
    float* out = (float*)d_out;                    // [NTOK, 1024]

    __half *xn, *xz, *y, *Win, *Wout, *wpack;
    cudaGetSymbolAddress((void**)&xn,    g_xn);
    cudaGetSymbolAddress((void**)&xz,    g_xz);
    cudaGetSymbolAddress((void**)&y,     g_y);
    cudaGetSymbolAddress((void**)&Win,   g_Win);
    cudaGetSymbolAddress((void**)&Wout,  g_Wout);
    cudaGetSymbolAddress((void**)&wpack, g_wpack);

    cudaFuncSetAttribute(gemm_f16_kernel<true>,
                         cudaFuncAttributeMaxDynamicSharedMemorySize, GEMM_SMEM_BYTES);
    cudaFuncSetAttribute(gemm_f16_kernel<false>,
                         cudaFuncAttributeMaxDynamicSharedMemorySize, GEMM_SMEM_BYTES);

    // 0) fused prep: weight fp16 conversions + conv weight pack
    prep_kernel<<<6145, 256>>>(W_in, W_out, conv_w, conv_b, Win, Wout, wpack);

    // 1) LayerNorm (fp16 output)
    ln_kernel<<<NTOK, 256>>>(x, gamma, beta, xn);

    // 2) in_proj GEMM: xz[16384,4096] (fp16) = xn @ Win^T
    {
        dim3 grid(2 * D_INNER / BN, NTOK / BM);   // (32, 128)
        gemm_f16_kernel<true><<<grid, 512, GEMM_SMEM_BYTES>>>(
            xn, Win, nullptr, xz, NTOK, 2 * D_INNER, D_MODEL);
    }

    // 3) causal depthwise conv + SiLU gate (fp16 y), fast MUFU silu
    conv_gate_kernel<<<NTOK, 256>>>(xz, wpack, y);

    // 4) out_proj GEMM + residual: out = x + y @ Wout^T (fp32 output)
    {
        dim3 grid(D_MODEL / BN, NTOK / BM);       // (8, 128)
        gemm_f16_kernel<false><<<grid, 512, GEMM_SMEM_BYTES>>>(
            y, Wout, x, out, NTOK, D_MODEL, D_INNER);
    }
}